// round 5
// baseline (speedup 1.0000x reference)
#include <cuda_runtime.h>
#include <cuda_bf16.h>

#define B   16
#define NQ  512
#define NK  1024
#define CIN 128
#define H   8
#define D   64
#define HD  (H * D)

#define LOG2E 1.4426950408889634f

// Scratch: Q/K/V in [b][h][row][d] layout
__device__ float g_Q[B * H * NQ * D];
__device__ float g_K[B * H * NK * D];
__device__ float g_V[B * H * NK * D];

typedef unsigned long long u64;

// ---- packed f32x2 helpers ----
__device__ __forceinline__ u64 pk2(float a) {
    u64 r; asm("mov.b64 %0,{%1,%1};" : "=l"(r) : "f"(a)); return r;
}
__device__ __forceinline__ void fma2(u64& d, u64 a, u64 b) {
    asm("fma.rn.f32x2 %0,%1,%2,%0;" : "+l"(d) : "l"(a), "l"(b));
}
__device__ __forceinline__ u64 add2(u64 a, u64 b) {
    u64 r; asm("add.rn.f32x2 %0,%1,%2;" : "=l"(r) : "l"(a), "l"(b)); return r;
}
__device__ __forceinline__ float2 upk(u64 v) {
    float lo, hi; asm("mov.b64 {%0,%1},%2;" : "=f"(lo), "=f"(hi) : "l"(v));
    return make_float2(lo, hi);
}
__device__ __forceinline__ float ex2(float x) {
    float r; asm("ex2.approx.f32 %0,%1;" : "=f"(r) : "f"(x)); return r;
}

// ---------------------------------------------------------------------------
// Q projection (FFMA2). scale folds 1/sqrt(D) * log2(e).
// ---------------------------------------------------------------------------
__global__ __launch_bounds__(128)
void projq_kernel(const float* __restrict__ X, const float* __restrict__ W,
                  const float* __restrict__ bias, float scale)
{
    __shared__ float xs[8][128];
    const int tid = threadIdx.x;
    const long row0 = (long)blockIdx.x * 8;

    #pragma unroll
    for (int r = 0; r < 8; r++)
        xs[r][tid] = X[(row0 + r) * CIN + tid];
    __syncthreads();

    u64 acc2[8][2];
    #pragma unroll
    for (int r = 0; r < 8; r++) { acc2[r][0] = 0ull; acc2[r][1] = 0ull; }

    const ulonglong2* __restrict__ W2 = (const ulonglong2*)W;
    #pragma unroll 4
    for (int c = 0; c < CIN; c++) {
        ulonglong2 wv = W2[c * 128 + tid];
        #pragma unroll
        for (int r = 0; r < 8; r++) {
            u64 xx = pk2(xs[r][c]);
            fma2(acc2[r][0], xx, wv.x);
            fma2(acc2[r][1], xx, wv.y);
        }
    }

    const float4 b4 = ((const float4*)bias)[tid];
    const int n = tid * 4, h = n >> 6, d = n & 63;

    #pragma unroll
    for (int r = 0; r < 8; r++) {
        long row = row0 + r;
        int  b  = (int)(row / NQ);
        int  lr = (int)(row % NQ);
        float2 lo = upk(acc2[r][0]);
        float2 hi = upk(acc2[r][1]);
        float4 o;
        o.x = (lo.x + b4.x) * scale;
        o.y = (lo.y + b4.y) * scale;
        o.z = (hi.x + b4.z) * scale;
        o.w = (hi.y + b4.w) * scale;
        ((float4*)g_Q)[((long)(b * H + h) * NQ + lr) * (D / 4) + (d >> 2)] = o;
    }
}

// ---------------------------------------------------------------------------
// Fused K+V projection: one X staging pass feeds both GEMMs.
// ---------------------------------------------------------------------------
__global__ __launch_bounds__(128)
void projkv_kernel(const float* __restrict__ X,
                   const float* __restrict__ Wk, const float* __restrict__ bk,
                   const float* __restrict__ Wv, const float* __restrict__ bv)
{
    __shared__ float xs[8][128];
    const int tid = threadIdx.x;
    const long row0 = (long)blockIdx.x * 8;

    #pragma unroll
    for (int r = 0; r < 8; r++)
        xs[r][tid] = X[(row0 + r) * CIN + tid];
    __syncthreads();

    u64 ak[8][2], av[8][2];
    #pragma unroll
    for (int r = 0; r < 8; r++) { ak[r][0]=ak[r][1]=av[r][0]=av[r][1]=0ull; }

    const ulonglong2* __restrict__ Wk2 = (const ulonglong2*)Wk;
    const ulonglong2* __restrict__ Wv2 = (const ulonglong2*)Wv;
    #pragma unroll 2
    for (int c = 0; c < CIN; c++) {
        ulonglong2 wk = Wk2[c * 128 + tid];
        ulonglong2 wv = Wv2[c * 128 + tid];
        #pragma unroll
        for (int r = 0; r < 8; r++) {
            u64 xx = pk2(xs[r][c]);
            fma2(ak[r][0], xx, wk.x);
            fma2(ak[r][1], xx, wk.y);
            fma2(av[r][0], xx, wv.x);
            fma2(av[r][1], xx, wv.y);
        }
    }

    const float4 bk4 = ((const float4*)bk)[tid];
    const float4 bv4 = ((const float4*)bv)[tid];
    const int n = tid * 4, h = n >> 6, d = n & 63;

    #pragma unroll
    for (int r = 0; r < 8; r++) {
        long row = row0 + r;
        int  b  = (int)(row / NK);
        int  lr = (int)(row % NK);
        long oidx = ((long)(b * H + h) * NK + lr) * (D / 4) + (d >> 2);
        float2 klo = upk(ak[r][0]), khi = upk(ak[r][1]);
        float2 vlo = upk(av[r][0]), vhi = upk(av[r][1]);
        ((float4*)g_K)[oidx] = make_float4(klo.x + bk4.x, klo.y + bk4.y,
                                           khi.x + bk4.z, khi.y + bk4.w);
        ((float4*)g_V)[oidx] = make_float4(vlo.x + bv4.x, vlo.y + bv4.y,
                                           vhi.x + bv4.z, vhi.y + bv4.w);
    }
}

// ---------------------------------------------------------------------------
// Fused attention, 256 threads/block, 128 queries x 64-key tiles.
// Phase A: S = Q.K^T, 4q x 8k/thread, f32x2. P stored [q][k] (contig stores).
// Phase B: O += P.V,  4q x 8d/thread, f32x2.
// exp via bare ex2 (log2e folded into Q scale + mask). lsum shfl at end only.
// ---------------------------------------------------------------------------
#define ATTN_SMEM ((64*128 + 64*64 + 64*64 + 128*64 + 64) * 4)

__global__ __launch_bounds__(256, 2)
void attn_kernel(const float* __restrict__ c_mask, float* __restrict__ out)
{
    extern __shared__ float sm[];
    float* Qs = sm;                 // [d][q]  64 x 128
    float* Ks = Qs + 64 * 128;      // [d][k]  64 x 64
    float* Vs = Ks + 64 * 64;       // [k][d]  64 x 64
    float* Ps = Vs + 64 * 64;       // [q][k]  128 x 64
    float* ms = Ps + 128 * 64;      // [k]     64

    const int tid = threadIdx.x;
    const int ty  = tid >> 3;       // 0..31 -> 4 queries
    const int tx  = tid & 7;        // 0..7  -> 8 keys / 8 dims
    const int h   = blockIdx.y;
    const int b   = blockIdx.z;
    const long bh = (long)b * H + h;
    const int q0  = blockIdx.x * 128;

    // Q tile transposed: Qs[d][q]. 2 threads per query row.
    {
        int q = tid >> 1, half = tid & 1;
        const float4* qg = (const float4*)&g_Q[(bh * NQ + q0 + q) * D];
        #pragma unroll
        for (int c4 = 0; c4 < 8; c4++) {
            float4 v = qg[half * 8 + c4];
            int c = half * 32 + c4 * 4;
            Qs[(c + 0) * 128 + q] = v.x;
            Qs[(c + 1) * 128 + q] = v.y;
            Qs[(c + 2) * 128 + q] = v.z;
            Qs[(c + 3) * 128 + q] = v.w;
        }
    }

    u64 o2[4][4];
    float lsum[4];
    #pragma unroll
    for (int i = 0; i < 4; i++) {
        lsum[i] = 0.f;
        #pragma unroll
        for (int p = 0; p < 4; p++) o2[i][p] = 0ull;
    }

    const float* __restrict__ mb = c_mask + (long)b * NK;
    const float4* Qs4 = (const float4*)Qs;
    const ulonglong2* Ks2 = (const ulonglong2*)Ks;
    const ulonglong2* Vs2 = (const ulonglong2*)Vs;
    float4* Ps4 = (float4*)Ps;

    #pragma unroll 1
    for (int kt = 0; kt < NK / 64; kt++) {
        __syncthreads();   // prev tile done with Ks/Vs/Ps

        // K transposed [d][k]: 4 threads per key row, 16 dims each
        {
            int k = tid & 63, qtr = tid >> 6;
            const float4* kg = (const float4*)&g_K[(bh * NK + kt * 64 + k) * D];
            #pragma unroll
            for (int c4 = 0; c4 < 4; c4++) {
                float4 v = kg[qtr * 4 + c4];
                int c = qtr * 16 + c4 * 4;
                Ks[(c + 0) * 64 + k] = v.x;
                Ks[(c + 1) * 64 + k] = v.y;
                Ks[(c + 2) * 64 + k] = v.z;
                Ks[(c + 3) * 64 + k] = v.w;
            }
        }
        // V natural [k][d], coalesced
        {
            const float4* vg = (const float4*)&g_V[(bh * NK + (long)kt * 64) * D];
            float4* Vs4 = (float4*)Vs;
            #pragma unroll
            for (int i = 0; i < 4; i++)
                Vs4[tid + i * 256] = vg[tid + i * 256];
        }
        if (tid < 64) ms[tid] = (-100000.f * LOG2E) * (1.f - mb[kt * 64 + tid]);
        __syncthreads();

        // ---- Phase A: S = Q.K^T (log2-domain scores) ----
        u64 s2[4][4];
        #pragma unroll
        for (int i = 0; i < 4; i++)
            #pragma unroll
            for (int p = 0; p < 4; p++) s2[i][p] = 0ull;

        #pragma unroll 4
        for (int c = 0; c < 64; c++) {
            float4 qv = Qs4[c * 32 + ty];
            ulonglong2 ka = Ks2[c * 16 + tx * 2];
            ulonglong2 kb = Ks2[c * 16 + tx * 2 + 1];
            float qf[4] = {qv.x, qv.y, qv.z, qv.w};
            #pragma unroll
            for (int i = 0; i < 4; i++) {
                u64 qq = pk2(qf[i]);
                fma2(s2[i][0], qq, ka.x);
                fma2(s2[i][1], qq, ka.y);
                fma2(s2[i][2], qq, kb.x);
                fma2(s2[i][3], qq, kb.y);
            }
        }

        // mask + exp2 + store P ([q][k], contiguous) + partial row sums
        ulonglong2 m01 = ((const ulonglong2*)ms)[tx * 2];
        ulonglong2 m23 = ((const ulonglong2*)ms)[tx * 2 + 1];
        #pragma unroll
        for (int i = 0; i < 4; i++) {
            float2 e0 = upk(add2(s2[i][0], m01.x));
            float2 e1 = upk(add2(s2[i][1], m01.y));
            float p0 = ex2(e0.x), p1 = ex2(e0.y), p2 = ex2(e1.x), p3 = ex2(e1.y);
            Ps4[(ty * 4 + i) * 16 + tx * 2] = make_float4(p0, p1, p2, p3);
            float2 e2 = upk(add2(s2[i][2], m23.x));
            float2 e3 = upk(add2(s2[i][3], m23.y));
            float p4 = ex2(e2.x), p5 = ex2(e2.y), p6 = ex2(e3.x), p7 = ex2(e3.y);
            Ps4[(ty * 4 + i) * 16 + tx * 2 + 1] = make_float4(p4, p5, p6, p7);
            lsum[i] += ((p0 + p1) + (p2 + p3)) + ((p4 + p5) + (p6 + p7));
        }
        __syncthreads();

        // ---- Phase B: O += P.V ----
        #pragma unroll 2
        for (int jj = 0; jj < 16; jj++) {
            float4 pv[4];
            #pragma unroll
            for (int i = 0; i < 4; i++)
                pv[i] = Ps4[(ty * 4 + i) * 16 + jj];
            #pragma unroll
            for (int r = 0; r < 4; r++) {
                ulonglong2 va = Vs2[(jj * 4 + r) * 16 + tx * 2];
                ulonglong2 vb = Vs2[(jj * 4 + r) * 16 + tx * 2 + 1];
                #pragma unroll
                for (int i = 0; i < 4; i++) {
                    float pe = (r == 0) ? pv[i].x : (r == 1) ? pv[i].y
                             : (r == 2) ? pv[i].z : pv[i].w;
                    u64 pp = pk2(pe);
                    fma2(o2[i][0], pp, va.x);
                    fma2(o2[i][1], pp, va.y);
                    fma2(o2[i][2], pp, vb.x);
                    fma2(o2[i][3], pp, vb.y);
                }
            }
        }
    }

    // Epilogue: single shfl reduction of lsum over the 8 tx lanes, then write.
    #pragma unroll
    for (int i = 0; i < 4; i++) {
        float r = lsum[i];
        r += __shfl_xor_sync(0xffffffffu, r, 1);
        r += __shfl_xor_sync(0xffffffffu, r, 2);
        r += __shfl_xor_sync(0xffffffffu, r, 4);
        float inv = 1.f / r;
        float2 a0 = upk(o2[i][0]);
        float2 a1 = upk(o2[i][1]);
        float2 a2 = upk(o2[i][2]);
        float2 a3 = upk(o2[i][3]);
        int q = q0 + ty * 4 + i;
        float4* op = (float4*)&out[((long)b * NQ + q) * HD + h * D + tx * 8];
        op[0] = make_float4(a0.x * inv, a0.y * inv, a1.x * inv, a1.y * inv);
        op[1] = make_float4(a2.x * inv, a2.y * inv, a3.x * inv, a3.y * inv);
    }
}

// ---------------------------------------------------------------------------
extern "C" void kernel_launch(void* const* d_in, const int* in_sizes, int n_in,
                              void* d_out, int out_size)
{
    const float* query  = (const float*)d_in[0];
    const float* key    = (const float*)d_in[1];
    const float* c_mask = (const float*)d_in[2];
    const float* Wq     = (const float*)d_in[3];
    const float* bq     = (const float*)d_in[4];
    const float* Wk     = (const float*)d_in[5];
    const float* bk     = (const float*)d_in[6];
    const float* Wv     = (const float*)d_in[7];
    const float* bv     = (const float*)d_in[8];
    float* out = (float*)d_out;

    cudaFuncSetAttribute(attn_kernel, cudaFuncAttributeMaxDynamicSharedMemorySize, ATTN_SMEM);

    // fold 1/sqrt(D) and log2(e) into Q so softmax is a bare ex2
    const float qscale = 0.125f * LOG2E;

    projq_kernel<<<(B * NQ) / 8, 128>>>(query, Wq, bq, qscale);
    projkv_kernel<<<(B * NK) / 8, 128>>>(key, Wk, bk, Wv, bv);

    dim3 grid(NQ / 128, H, B);
    attn_kernel<<<grid, 256, ATTN_SMEM>>>(c_mask, out);
}

// round 10
// speedup vs baseline: 2.3167x; 2.3167x over previous
#include <cuda_runtime.h>
#include <cuda_bf16.h>
#include <cstdint>

#define B   16
#define NQ  512
#define NK  1024
#define CIN 128
#define H   8
#define D   64
#define HD  512
#define LOG2E 1.4426950408889634f

// Scratch: Q/K/V fp32 in [b][h][row][d] layout
__device__ float g_Q[B * H * NQ * D];
__device__ float g_K[B * H * NK * D];
__device__ float g_V[B * H * NK * D];

typedef unsigned long long u64;

// ============================ helpers ============================
__device__ __forceinline__ uint32_t smem_u32(const void* p) {
    uint32_t a;
    asm("{ .reg .u64 t; cvta.to.shared.u64 t, %1; cvt.u32.u64 %0, t; }" : "=r"(a) : "l"(p));
    return a;
}
#define SWZ(off) ((off) ^ (((off) >> 3) & 0x70))

// pack 2 floats -> bf16x2 (lo = x, hi = y)
__device__ __forceinline__ uint32_t packbf(float x, float y) {
    uint32_t r; asm("cvt.rn.bf16x2.f32 %0,%1,%2;" : "=r"(r) : "f"(y), "f"(x)); return r;
}
__device__ __forceinline__ float ex2(float x) {
    float r; asm("ex2.approx.f32 %0,%1;" : "=f"(r) : "f"(x)); return r;
}
__device__ __forceinline__ float bfround(float x) {
    return __bfloat162float(__float2bfloat16(x));
}

// ldmatrix x4 (non-trans / trans)
__device__ __forceinline__ void ldsm4(uint32_t (&r)[4], uint32_t a) {
    asm volatile("ldmatrix.sync.aligned.m8n8.x4.shared.b16 {%0,%1,%2,%3},[%4];"
        : "=r"(r[0]), "=r"(r[1]), "=r"(r[2]), "=r"(r[3]) : "r"(a));
}
__device__ __forceinline__ void ldsm4t(uint32_t (&r)[4], uint32_t a) {
    asm volatile("ldmatrix.sync.aligned.m8n8.x4.trans.shared.b16 {%0,%1,%2,%3},[%4];"
        : "=r"(r[0]), "=r"(r[1]), "=r"(r[2]), "=r"(r[3]) : "r"(a));
}

// mma m16n8k16 bf16 -> f32
__device__ __forceinline__ void mma16816(float (&c)[4], const uint32_t (&a)[4],
                                         uint32_t b0, uint32_t b1) {
    asm volatile("mma.sync.aligned.m16n8k16.row.col.f32.bf16.bf16.f32 "
        "{%0,%1,%2,%3},{%4,%5,%6,%7},{%8,%9},{%0,%1,%2,%3};"
        : "+f"(c[0]), "+f"(c[1]), "+f"(c[2]), "+f"(c[3])
        : "r"(a[0]), "r"(a[1]), "r"(a[2]), "r"(a[3]), "r"(b0), "r"(b1));
}

// ---- packed f32x2 helpers (projection kernels) ----
__device__ __forceinline__ u64 pk2(float a) {
    u64 r; asm("mov.b64 %0,{%1,%1};" : "=l"(r) : "f"(a)); return r;
}
__device__ __forceinline__ void fma2(u64& d, u64 a, u64 b) {
    asm("fma.rn.f32x2 %0,%1,%2,%0;" : "+l"(d) : "l"(a), "l"(b));
}
__device__ __forceinline__ float2 upk(u64 v) {
    float lo, hi; asm("mov.b64 {%0,%1},%2;" : "=f"(lo), "=f"(hi) : "l"(v));
    return make_float2(lo, hi);
}

// ============================ projections ============================
__global__ __launch_bounds__(128)
void projq_kernel(const float* __restrict__ X, const float* __restrict__ W,
                  const float* __restrict__ bias, float scale)
{
    __shared__ float xs[8][128];
    const int tid = threadIdx.x;
    const long row0 = (long)blockIdx.x * 8;

    #pragma unroll
    for (int r = 0; r < 8; r++)
        xs[r][tid] = X[(row0 + r) * CIN + tid];
    __syncthreads();

    u64 acc2[8][2];
    #pragma unroll
    for (int r = 0; r < 8; r++) { acc2[r][0] = 0ull; acc2[r][1] = 0ull; }

    const ulonglong2* __restrict__ W2 = (const ulonglong2*)W;
    #pragma unroll 4
    for (int c = 0; c < CIN; c++) {
        ulonglong2 wv = W2[c * 128 + tid];
        #pragma unroll
        for (int r = 0; r < 8; r++) {
            u64 xx = pk2(xs[r][c]);
            fma2(acc2[r][0], xx, wv.x);
            fma2(acc2[r][1], xx, wv.y);
        }
    }

    const float4 b4 = ((const float4*)bias)[tid];
    const int n = tid * 4, h = n >> 6, d = n & 63;

    #pragma unroll
    for (int r = 0; r < 8; r++) {
        long row = row0 + r;
        int  b  = (int)(row / NQ);
        int  lr = (int)(row % NQ);
        float2 lo = upk(acc2[r][0]);
        float2 hi = upk(acc2[r][1]);
        float4 o;
        o.x = (lo.x + b4.x) * scale;
        o.y = (lo.y + b4.y) * scale;
        o.z = (hi.x + b4.z) * scale;
        o.w = (hi.y + b4.w) * scale;
        ((float4*)g_Q)[((long)(b * H + h) * NQ + lr) * (D / 4) + (d >> 2)] = o;
    }
}

__global__ __launch_bounds__(128)
void projkv_kernel(const float* __restrict__ X,
                   const float* __restrict__ Wk, const float* __restrict__ bk,
                   const float* __restrict__ Wv, const float* __restrict__ bv)
{
    __shared__ float xs[8][128];
    const int tid = threadIdx.x;
    const long row0 = (long)blockIdx.x * 8;

    #pragma unroll
    for (int r = 0; r < 8; r++)
        xs[r][tid] = X[(row0 + r) * CIN + tid];
    __syncthreads();

    u64 ak[8][2], av[8][2];
    #pragma unroll
    for (int r = 0; r < 8; r++) { ak[r][0]=ak[r][1]=av[r][0]=av[r][1]=0ull; }

    const ulonglong2* __restrict__ Wk2 = (const ulonglong2*)Wk;
    const ulonglong2* __restrict__ Wv2 = (const ulonglong2*)Wv;
    #pragma unroll 2
    for (int c = 0; c < CIN; c++) {
        ulonglong2 wk = Wk2[c * 128 + tid];
        ulonglong2 wv = Wv2[c * 128 + tid];
        #pragma unroll
        for (int r = 0; r < 8; r++) {
            u64 xx = pk2(xs[r][c]);
            fma2(ak[r][0], xx, wk.x);
            fma2(ak[r][1], xx, wk.y);
            fma2(av[r][0], xx, wv.x);
            fma2(av[r][1], xx, wv.y);
        }
    }

    const float4 bk4 = ((const float4*)bk)[tid];
    const float4 bv4 = ((const float4*)bv)[tid];
    const int n = tid * 4, h = n >> 6, d = n & 63;

    #pragma unroll
    for (int r = 0; r < 8; r++) {
        long row = row0 + r;
        int  b  = (int)(row / NK);
        int  lr = (int)(row % NK);
        long oidx = ((long)(b * H + h) * NK + lr) * (D / 4) + (d >> 2);
        float2 klo = upk(ak[r][0]), khi = upk(ak[r][1]);
        float2 vlo = upk(av[r][0]), vhi = upk(av[r][1]);
        ((float4*)g_K)[oidx] = make_float4(klo.x + bk4.x, klo.y + bk4.y,
                                           khi.x + bk4.z, khi.y + bk4.w);
        ((float4*)g_V)[oidx] = make_float4(vlo.x + bv4.x, vlo.y + bv4.y,
                                           vhi.x + bv4.z, vhi.y + bv4.w);
    }
}

// ============================ mma.sync attention ============================
// 256 threads = 8 warps. Block handles 128 queries x one (b,h).
// Warp w owns q rows [q0 + 16w, +16). Per 64-key tile:
//   S(16x64) = Q.K^T  (bf16 mma, fp32 acc, 32 mma)
//   p = ex2(S + mask) in C-fragments; C-frag layout == A-frag layout,
//   so P feeds the PV mma directly from registers (FA2 trick).
//   O(16x64) += Phi.Vhi + Phi.Vlo + Plo.Vhi  (V split hi/lo bf16, 96 mma)
__global__ __launch_bounds__(256)
void attn_kernel(const float* __restrict__ c_mask, float* __restrict__ out)
{
    __shared__ __align__(128) uint8_t smK [64 * 128];  // bf16 [key][64d]
    __shared__ __align__(128) uint8_t smVh[64 * 128];  // bf16 hi
    __shared__ __align__(128) uint8_t smVl[64 * 128];  // bf16 lo
    __shared__ float msf[64];

    const int tid  = threadIdx.x;
    const int w    = tid >> 5;
    const int lane = tid & 31;
    const int g = lane >> 2, t = lane & 3;
    const int h = blockIdx.y, b = blockIdx.z;
    const long bh = (long)b * H + h;
    const int q0 = blockIdx.x * 128;

    // ---- preload Q A-fragments (4 k-chunks x 4 regs), direct from global ----
    uint32_t qa[4][4];
    {
        const float* Qb = &g_Q[(bh * NQ + q0 + w * 16) * D];
        #pragma unroll
        for (int kc = 0; kc < 4; kc++) {
            float2 v0 = *(const float2*)&Qb[ g      * D + kc * 16 + 2 * t];
            float2 v1 = *(const float2*)&Qb[(g + 8) * D + kc * 16 + 2 * t];
            float2 v2 = *(const float2*)&Qb[ g      * D + kc * 16 + 8 + 2 * t];
            float2 v3 = *(const float2*)&Qb[(g + 8) * D + kc * 16 + 8 + 2 * t];
            qa[kc][0] = packbf(v0.x, v0.y);
            qa[kc][1] = packbf(v1.x, v1.y);
            qa[kc][2] = packbf(v2.x, v2.y);
            qa[kc][3] = packbf(v3.x, v3.y);
        }
    }

    float oacc[8][4];
    #pragma unroll
    for (int n = 0; n < 8; n++)
        #pragma unroll
        for (int i = 0; i < 4; i++) oacc[n][i] = 0.f;
    float lg = 0.f, lh = 0.f;

    const float* __restrict__ mb = c_mask + (long)b * NK;
    const uint32_t skb = smem_u32(smK);
    const uint32_t svh = smem_u32(smVh);
    const uint32_t svl = smem_u32(smVl);

    // ldmatrix lane-address components
    const int kRow = (lane & 7) + ((lane >> 4) & 1) * 8;   // S-gemm B (non-trans)
    const int kCol = (lane >> 3) & 1;
    const int vRow = (lane & 7) + ((lane >> 3) & 1) * 8;   // PV B (trans)
    const int vCol = lane >> 4;

    #pragma unroll 1
    for (int kt = 0; kt < NK / 64; kt++) {
        __syncthreads();   // previous tile's compute done reading smem

        // ---- stage K / Vhi / Vlo (bf16, SW128) + mask ----
        {
            int key = tid >> 2, q4 = tid & 3;
            const float4* ks = (const float4*)&g_K[(bh * NK + kt * 64 + key) * D + q4 * 16];
            const float4* vs = (const float4*)&g_V[(bh * NK + kt * 64 + key) * D + q4 * 16];
            #pragma unroll
            for (int i = 0; i < 2; i++) {
                float4 x = ks[i * 2], y = ks[i * 2 + 1];
                uint4 kv;
                kv.x = packbf(x.x, x.y);  kv.y = packbf(x.z, x.w);
                kv.z = packbf(y.x, y.y);  kv.w = packbf(y.z, y.w);
                *(uint4*)(smK + SWZ((uint32_t)key * 128 + q4 * 32 + i * 16)) = kv;
            }
            #pragma unroll
            for (int i = 0; i < 2; i++) {
                float4 x = vs[i * 2], y = vs[i * 2 + 1];
                float vv[8] = {x.x, x.y, x.z, x.w, y.x, y.y, y.z, y.w};
                uint4 hw, lw;
                uint32_t* hp = (uint32_t*)&hw;
                uint32_t* lp = (uint32_t*)&lw;
                #pragma unroll
                for (int e = 0; e < 4; e++) {
                    float h0 = bfround(vv[2 * e]);
                    float h1 = bfround(vv[2 * e + 1]);
                    hp[e] = packbf(h0, h1);
                    lp[e] = packbf(vv[2 * e] - h0, vv[2 * e + 1] - h1);
                }
                uint32_t off = SWZ((uint32_t)key * 128 + q4 * 32 + i * 16);
                *(uint4*)(smVh + off) = hw;
                *(uint4*)(smVl + off) = lw;
            }
        }
        if (tid < 64)
            msf[tid] = (-100000.f * LOG2E) * (1.f - mb[kt * 64 + tid]);
        __syncthreads();

        // ---- S = Q . K^T ----
        float sacc[8][4];
        #pragma unroll
        for (int n = 0; n < 8; n++)
            #pragma unroll
            for (int i = 0; i < 4; i++) sacc[n][i] = 0.f;

        #pragma unroll
        for (int kc = 0; kc < 4; kc++) {
            #pragma unroll
            for (int kp = 0; kp < 4; kp++) {
                uint32_t r[4];
                ldsm4(r, skb + SWZ((uint32_t)(16 * kp + kRow) * 128 + (2 * kc + kCol) * 16));
                mma16816(sacc[2 * kp],     qa[kc], r[0], r[1]);
                mma16816(sacc[2 * kp + 1], qa[kc], r[2], r[3]);
            }
        }

        // ---- softmax: p = ex2(s + m); build P A-fragments hi/lo ----
        uint32_t pahi[4][4], palo[4][4];
        #pragma unroll
        for (int n = 0; n < 8; n++) {
            float2 mv = *(const float2*)&msf[8 * n + 2 * t];
            float p0 = ex2(sacc[n][0] + mv.x);
            float p1 = ex2(sacc[n][1] + mv.y);
            float p2 = ex2(sacc[n][2] + mv.x);
            float p3 = ex2(sacc[n][3] + mv.y);
            lg += p0 + p1;
            lh += p2 + p3;
            float h0 = bfround(p0), h1 = bfround(p1);
            float h2 = bfround(p2), h3 = bfround(p3);
            int kc = n >> 1, hi = (n & 1) * 2;
            pahi[kc][hi]     = packbf(h0, h1);
            pahi[kc][hi + 1] = packbf(h2, h3);
            palo[kc][hi]     = packbf(p0 - h0, p1 - h1);
            palo[kc][hi + 1] = packbf(p2 - h2, p3 - h3);
        }

        // ---- O += Phi.Vhi + Plo.Vhi + Phi.Vlo ----
        #pragma unroll
        for (int kc = 0; kc < 4; kc++) {
            uint32_t vh[8][2], vl[8][2];
            #pragma unroll
            for (int dp = 0; dp < 4; dp++) {
                uint32_t off = SWZ((uint32_t)(16 * kc + vRow) * 128 + (2 * dp + vCol) * 16);
                uint32_t r[4];
                ldsm4t(r, svh + off);
                vh[2 * dp][0] = r[0]; vh[2 * dp][1] = r[1];
                vh[2 * dp + 1][0] = r[2]; vh[2 * dp + 1][1] = r[3];
                ldsm4t(r, svl + off);
                vl[2 * dp][0] = r[0]; vl[2 * dp][1] = r[1];
                vl[2 * dp + 1][0] = r[2]; vl[2 * dp + 1][1] = r[3];
            }
            #pragma unroll
            for (int n = 0; n < 8; n++) {
                mma16816(oacc[n], pahi[kc], vh[n][0], vh[n][1]);
                mma16816(oacc[n], palo[kc], vh[n][0], vh[n][1]);
                mma16816(oacc[n], pahi[kc], vl[n][0], vl[n][1]);
            }
        }
    }

    // ---- finalize: reduce row sums over the 4-lane group, normalize, write ----
    lg += __shfl_xor_sync(0xffffffffu, lg, 1);
    lg += __shfl_xor_sync(0xffffffffu, lg, 2);
    lh += __shfl_xor_sync(0xffffffffu, lh, 1);
    lh += __shfl_xor_sync(0xffffffffu, lh, 2);
    float ig = 1.f / lg, ih = 1.f / lh;

    float* og = &out[((long)b * NQ + q0 + w * 16 + g)     * HD + h * D];
    float* oh = &out[((long)b * NQ + q0 + w * 16 + g + 8) * HD + h * D];
    #pragma unroll
    for (int n = 0; n < 8; n++) {
        *(float2*)&og[8 * n + 2 * t] = make_float2(oacc[n][0] * ig, oacc[n][1] * ig);
        *(float2*)&oh[8 * n + 2 * t] = make_float2(oacc[n][2] * ih, oacc[n][3] * ih);
    }
}

// ---------------------------------------------------------------------------
extern "C" void kernel_launch(void* const* d_in, const int* in_sizes, int n_in,
                              void* d_out, int out_size)
{
    const float* query  = (const float*)d_in[0];
    const float* key    = (const float*)d_in[1];
    const float* c_mask = (const float*)d_in[2];
    const float* Wq     = (const float*)d_in[3];
    const float* bq     = (const float*)d_in[4];
    const float* Wk     = (const float*)d_in[5];
    const float* bk     = (const float*)d_in[6];
    const float* Wv     = (const float*)d_in[7];
    const float* bv     = (const float*)d_in[8];
    float* out = (float*)d_out;

    // fold 1/sqrt(D) and log2(e) into Q so softmax is a bare ex2
    const float qscale = 0.125f * LOG2E;

    projq_kernel<<<(B * NQ) / 8, 128>>>(query, Wq, bq, qscale);
    projkv_kernel<<<(B * NK) / 8, 128>>>(key, Wk, bk, Wv, bv);

    dim3 grid(NQ / 128, H, B);
    attn_kernel<<<grid, 256>>>(c_mask, out);
}